// round 10
// baseline (speedup 1.0000x reference)
#include <cuda_runtime.h>
#include <cuda_fp8.h>
#include <cuda_fp16.h>
#include <cstdint>
#include <math.h>

#define Bb 2
#define Tt 1024
#define Cdim 2048
#define Hh 16
#define HDim 128
#define MLPD 8192
#define Mrows (Bb * Tt)

__device__ float g_xdq[Mrows * Cdim];
__device__ float g_hdq[Mrows * MLPD];
__device__ float g_q[Mrows * Cdim];
__device__ float g_k[Mrows * Cdim];
__device__ float g_v[Mrows * Cdim];
__device__ float g_scores[(size_t)Bb * Hh * Tt * Tt];
__device__ float g_ctx[Mrows * Cdim];
__device__ float g_tmp[Mrows * Cdim];
__device__ float g_x1[Mrows * Cdim];
__device__ float g_h[Mrows * MLPD];
__device__ float g_ffn[Mrows * Cdim];
__device__ __half g_f2h[Cdim * MLPD];   // fp16 fc2 weights (exact: fp8-valued)

// ---------------------------------------------------------------------------
// mma.sync helpers (sm_80-baseline PTX; legal at compute_103)
// ---------------------------------------------------------------------------
__device__ __forceinline__ uint32_t smem_u32(const void* p) {
    uint32_t a;
    asm("{ .reg .u64 t; cvta.to.shared.u64 t, %1; cvt.u32.u64 %0, t; }" : "=r"(a) : "l"(p));
    return a;
}
__device__ __forceinline__ void ldsm4(uint32_t& r0, uint32_t& r1, uint32_t& r2, uint32_t& r3,
                                      uint32_t addr) {
    asm volatile("ldmatrix.sync.aligned.m8n8.x4.shared.b16 {%0,%1,%2,%3}, [%4];"
                 : "=r"(r0), "=r"(r1), "=r"(r2), "=r"(r3) : "r"(addr));
}
__device__ __forceinline__ void mma16816(float* c, const uint32_t* a, uint32_t b0, uint32_t b1) {
    asm volatile("mma.sync.aligned.m16n8k16.row.col.f32.f16.f16.f32 "
                 "{%0,%1,%2,%3}, {%4,%5,%6,%7}, {%8,%9}, {%0,%1,%2,%3};"
                 : "+f"(c[0]), "+f"(c[1]), "+f"(c[2]), "+f"(c[3])
                 : "r"(a[0]), "r"(a[1]), "r"(a[2]), "r"(a[3]), "r"(b0), "r"(b1));
}
__device__ __forceinline__ int swz(int byte_off) {
    return byte_off ^ ((byte_off >> 3) & 0x70);
}
__device__ __forceinline__ uint32_t pack_f16(float a, float b) {
    __half2 h = __floats2half2_rn(a, b);
    return *reinterpret_cast<uint32_t*>(&h);
}
__device__ __forceinline__ float f16_of(uint32_t h, int odd) {
    uint16_t hu = odd ? (uint16_t)(h >> 16) : (uint16_t)(h & 0xffff);
    __half v = *reinterpret_cast<__half*>(&hu);
    return __half2float(v);
}

// ---------------------------------------------------------------------------
// fp32 quantize-dequantize (bit-identical to passing R1/R9)
// ---------------------------------------------------------------------------
__global__ void qdq_kernel(const float* __restrict__ in, float* __restrict__ out,
                           float fmax, int e4m3)
{
    int blk  = blockIdx.x * 8 + (threadIdx.x >> 5);
    int lane = threadIdx.x & 31;
    size_t base = (size_t)blk * 128 + (size_t)lane * 4;
    float4 v = *reinterpret_cast<const float4*>(in + base);
    float am = fmaxf(fmaxf(fabsf(v.x), fabsf(v.y)), fmaxf(fabsf(v.z), fabsf(v.w)));
    #pragma unroll
    for (int o = 16; o > 0; o >>= 1)
        am = fmaxf(am, __shfl_xor_sync(0xffffffffu, am, o));
    float s = fmaxf(am / fmax, 1e-12f);
    float r4[4]; float xin[4] = {v.x, v.y, v.z, v.w};
    #pragma unroll
    for (int i = 0; i < 4; i++) {
        float r = xin[i] / s;
        __nv_fp8_storage_t f8 = __nv_cvt_float_to_fp8(r, __NV_SATFINITE, e4m3 ? __NV_E4M3 : __NV_E5M2);
        __half_raw hr = __nv_cvt_fp8_to_halfraw(f8, e4m3 ? __NV_E4M3 : __NV_E5M2);
        r4[i] = __half2float(*reinterpret_cast<__half*>(&hr)) * s;
    }
    float4 o4 = {r4[0], r4[1], r4[2], r4[3]};
    *reinterpret_cast<float4*>(out + base) = o4;
}

// f32 -> fp16 (exact for fp8-valued weights)
__global__ void conv_f16(const float* __restrict__ in, __half* __restrict__ out, int n4)
{
    int i = blockIdx.x * blockDim.x + threadIdx.x;
    if (i >= n4) return;
    float4 v = reinterpret_cast<const float4*>(in)[i];
    __half b[4] = {__float2half_rn(v.x), __float2half_rn(v.y),
                   __float2half_rn(v.z), __float2half_rn(v.w)};
    reinterpret_cast<uint2*>(out)[i] = *reinterpret_cast<uint2*>(b);
}

// ---------------------------------------------------------------------------
// Split-fp16 mma GEMM (NT) — used ONLY for fc2 (no qdq downstream).
// A fp32 split hi+lo fp16 (2 mma); W exact fp16. 128x128 tile, 512 thr, BK=64.
// ---------------------------------------------------------------------------
#define WAH 0
#define WAL 16384
#define WB  32768
#define WBUF 49152
#define W_SMEM (2 * WBUF)

__global__ void __launch_bounds__(512, 1)
wgemm(const float* __restrict__ A, const __half* __restrict__ W, float* __restrict__ C,
      int K, int N,
      const float* __restrict__ wscale, const float* __restrict__ bias, int act)
{
    extern __shared__ char sm[];
    uint32_t smb = smem_u32(sm);
    int tid = threadIdx.x, lane = tid & 31, wid = tid >> 5;
    int wm = wid & 3, wn = wid >> 2;
    int m0 = blockIdx.y * 128, n0 = blockIdx.x * 128;

    int lr = tid >> 2, lq = tid & 3;
    const float* gA = A + (size_t)(m0 + lr) * K + lq * 16;
    const char*  gB = (const char*)(W + (size_t)(n0 + lr) * K) + lq * 32;
    int so0 = swz(lr * 128 + lq * 32);
    int so1 = swz(lr * 128 + lq * 32 + 16);

    float acc[2][4][4];
    #pragma unroll
    for (int mt = 0; mt < 2; mt++)
        #pragma unroll
        for (int nt = 0; nt < 4; nt++)
            #pragma unroll
            for (int i = 0; i < 4; i++) acc[mt][nt][i] = 0.0f;

    float4 f0 = *(const float4*)(gA);
    float4 f1 = *(const float4*)(gA + 4);
    float4 f2 = *(const float4*)(gA + 8);
    float4 f3 = *(const float4*)(gA + 12);
    uint4 wb0 = *(const uint4*)(gB), wb1 = *(const uint4*)(gB + 16);
    {
        uint4 hA = {pack_f16(f0.x, f0.y), pack_f16(f0.z, f0.w), pack_f16(f1.x, f1.y), pack_f16(f1.z, f1.w)};
        uint4 hB = {pack_f16(f2.x, f2.y), pack_f16(f2.z, f2.w), pack_f16(f3.x, f3.y), pack_f16(f3.z, f3.w)};
        float r[16] = {f0.x,f0.y,f0.z,f0.w,f1.x,f1.y,f1.z,f1.w,f2.x,f2.y,f2.z,f2.w,f3.x,f3.y,f3.z,f3.w};
        #pragma unroll
        for (int i = 0; i < 16; i++) {
            uint32_t h = (i < 8) ? (&hA.x)[i >> 1] : (&hB.x)[(i - 8) >> 1];
            r[i] = r[i] - f16_of(h, i & 1);
        }
        uint4 lA = {pack_f16(r[0], r[1]), pack_f16(r[2], r[3]), pack_f16(r[4], r[5]), pack_f16(r[6], r[7])};
        uint4 lB = {pack_f16(r[8], r[9]), pack_f16(r[10], r[11]), pack_f16(r[12], r[13]), pack_f16(r[14], r[15])};
        *(uint4*)(sm + WAH + so0) = hA; *(uint4*)(sm + WAH + so1) = hB;
        *(uint4*)(sm + WAL + so0) = lA; *(uint4*)(sm + WAL + so1) = lB;
        *(uint4*)(sm + WB + so0) = wb0; *(uint4*)(sm + WB + so1) = wb1;
    }
    __syncthreads();

    int nkt = K >> 6;
    for (int kt = 0; kt < nkt; kt++) {
        int cur = kt & 1;
        bool pf = (kt + 1) < nkt;
        if (pf) {
            const float* pA = gA + (kt + 1) * 64;
            const char*  pB = gB + (size_t)(kt + 1) * 128;
            f0 = *(const float4*)(pA);      f1 = *(const float4*)(pA + 4);
            f2 = *(const float4*)(pA + 8);  f3 = *(const float4*)(pA + 12);
            wb0 = *(const uint4*)(pB);      wb1 = *(const uint4*)(pB + 16);
        }
        uint32_t hbase = smb + cur * WBUF + WAH;
        uint32_t lbase = smb + cur * WBUF + WAL;
        uint32_t bbase = smb + cur * WBUF + WB;
        #pragma unroll
        for (int ks = 0; ks < 4; ks++) {
            int kbyte = ks * 32 + (lane >> 4) * 16;
            uint32_t ah[2][4], al[2][4], br[2][4];
            #pragma unroll
            for (int mt = 0; mt < 2; mt++) {
                int ro = swz((wm * 32 + mt * 16 + (lane & 15)) * 128 + kbyte);
                ldsm4(ah[mt][0], ah[mt][1], ah[mt][2], ah[mt][3], hbase + ro);
                ldsm4(al[mt][0], al[mt][1], al[mt][2], al[mt][3], lbase + ro);
            }
            #pragma unroll
            for (int ng = 0; ng < 2; ng++)
                ldsm4(br[ng][0], br[ng][1], br[ng][2], br[ng][3],
                      bbase + swz((wn * 32 + ng * 16 + (lane & 15)) * 128 + kbyte));
            #pragma unroll
            for (int mt = 0; mt < 2; mt++)
                #pragma unroll
                for (int nt = 0; nt < 4; nt++) {
                    int ng = nt >> 1, hf = nt & 1;
                    mma16816(acc[mt][nt], ah[mt], br[ng][hf], br[ng][2 + hf]);
                    mma16816(acc[mt][nt], al[mt], br[ng][hf], br[ng][2 + hf]);
                }
        }
        __syncthreads();
        if (pf) {
            char* dst = sm + (cur ^ 1) * WBUF;
            uint4 hA = {pack_f16(f0.x, f0.y), pack_f16(f0.z, f0.w), pack_f16(f1.x, f1.y), pack_f16(f1.z, f1.w)};
            uint4 hB = {pack_f16(f2.x, f2.y), pack_f16(f2.z, f2.w), pack_f16(f3.x, f3.y), pack_f16(f3.z, f3.w)};
            float r[16] = {f0.x,f0.y,f0.z,f0.w,f1.x,f1.y,f1.z,f1.w,f2.x,f2.y,f2.z,f2.w,f3.x,f3.y,f3.z,f3.w};
            #pragma unroll
            for (int i = 0; i < 16; i++) {
                uint32_t h = (i < 8) ? (&hA.x)[i >> 1] : (&hB.x)[(i - 8) >> 1];
                r[i] = r[i] - f16_of(h, i & 1);
            }
            uint4 lA = {pack_f16(r[0], r[1]), pack_f16(r[2], r[3]), pack_f16(r[4], r[5]), pack_f16(r[6], r[7])};
            uint4 lB = {pack_f16(r[8], r[9]), pack_f16(r[10], r[11]), pack_f16(r[12], r[13]), pack_f16(r[14], r[15])};
            *(uint4*)(dst + WAH + so0) = hA; *(uint4*)(dst + WAH + so1) = hB;
            *(uint4*)(dst + WAL + so0) = lA; *(uint4*)(dst + WAL + so1) = lB;
            *(uint4*)(dst + WB + so0) = wb0; *(uint4*)(dst + WB + so1) = wb1;
            __syncthreads();
        }
    }

    float ws = wscale ? wscale[n0 >> 7] : 1.0f;
    #pragma unroll
    for (int mt = 0; mt < 2; mt++) {
        int row = m0 + wm * 32 + mt * 16 + (lane >> 2);
        #pragma unroll
        for (int nt = 0; nt < 4; nt++) {
            int col = n0 + wn * 32 + nt * 8 + (lane & 3) * 2;
            float v0 = acc[mt][nt][0] * ws, v1 = acc[mt][nt][1] * ws;
            float v2 = acc[mt][nt][2] * ws, v3 = acc[mt][nt][3] * ws;
            if (bias) { float b0 = bias[col], b1 = bias[col + 1]; v0 += b0; v1 += b1; v2 += b0; v3 += b1; }
            if (act) {
                v0 = 0.5f * v0 * (1.0f + erff(v0 * 0.7071067811865476f));
                v1 = 0.5f * v1 * (1.0f + erff(v1 * 0.7071067811865476f));
                v2 = 0.5f * v2 * (1.0f + erff(v2 * 0.7071067811865476f));
                v3 = 0.5f * v3 * (1.0f + erff(v3 * 0.7071067811865476f));
            }
            *reinterpret_cast<float2*>(C + (size_t)row * N + col)       = make_float2(v0, v1);
            *reinterpret_cast<float2*>(C + (size_t)(row + 8) * N + col) = make_float2(v2, v3);
        }
    }
}

// ---------------------------------------------------------------------------
// Double-buffered fp32 SGEMM NT (verbatim R9)
// ---------------------------------------------------------------------------
__global__ void __launch_bounds__(256, 2)
gemm_nt(const float* __restrict__ A, const float* __restrict__ W, float* __restrict__ C,
        int K, int lda, int ldb, int ldc,
        int zdiv, long long sA1, long long sA2, long long sB1, long long sB2,
        long long sC1, long long sC2,
        const float* __restrict__ wscale, const float* __restrict__ bias,
        int act, int causal)
{
    __shared__ float As[2][8][132];
    __shared__ float Bs[2][8][132];
    int z = blockIdx.z;
    int z1 = z / zdiv, z2 = z % zdiv;
    A += z1 * sA1 + z2 * sA2;
    W += z1 * sB1 + z2 * sB2;
    C += z1 * sC1 + z2 * sC2;

    int m0 = blockIdx.y * 128, n0 = blockIdx.x * 128;
    if (causal && n0 > m0 + 127) return;

    int tid = threadIdx.x;
    int tx = tid & 15, ty = tid >> 4;
    int lrow = tid >> 1, lcol = (tid & 1) * 4;
    const float* gA = A + (size_t)(m0 + lrow) * lda + lcol;
    const float* gB = W + (size_t)(n0 + lrow) * ldb + lcol;

    float acc[8][8];
    #pragma unroll
    for (int i = 0; i < 8; i++)
        #pragma unroll
        for (int j = 0; j < 8; j++) acc[i][j] = 0.0f;

    float4 av = *reinterpret_cast<const float4*>(gA);
    float4 bv = *reinterpret_cast<const float4*>(gB);
    As[0][lcol + 0][lrow] = av.x; As[0][lcol + 1][lrow] = av.y;
    As[0][lcol + 2][lrow] = av.z; As[0][lcol + 3][lrow] = av.w;
    Bs[0][lcol + 0][lrow] = bv.x; Bs[0][lcol + 1][lrow] = bv.y;
    Bs[0][lcol + 2][lrow] = bv.z; Bs[0][lcol + 3][lrow] = bv.w;
    __syncthreads();

    int nkt = K >> 3;
    for (int kt = 0; kt < nkt; kt++) {
        int cur = kt & 1;
        bool pf = (kt + 1) < nkt;
        if (pf) {
            av = *reinterpret_cast<const float4*>(gA + (kt + 1) * 8);
            bv = *reinterpret_cast<const float4*>(gB + (kt + 1) * 8);
        }
        #pragma unroll
        for (int kk = 0; kk < 8; kk++) {
            float4 a0 = *reinterpret_cast<const float4*>(&As[cur][kk][ty * 8]);
            float4 a1 = *reinterpret_cast<const float4*>(&As[cur][kk][ty * 8 + 4]);
            float4 b0 = *reinterpret_cast<const float4*>(&Bs[cur][kk][tx * 8]);
            float4 b1 = *reinterpret_cast<const float4*>(&Bs[cur][kk][tx * 8 + 4]);
            float a[8] = {a0.x, a0.y, a0.z, a0.w, a1.x, a1.y, a1.z, a1.w};
            float b[8] = {b0.x, b0.y, b0.z, b0.w, b1.x, b1.y, b1.z, b1.w};
            #pragma unroll
            for (int i = 0; i < 8; i++)
                #pragma unroll
                for (int j = 0; j < 8; j++) acc[i][j] = fmaf(a[i], b[j], acc[i][j]);
        }
        if (pf) {
            int nb = cur ^ 1;
            As[nb][lcol + 0][lrow] = av.x; As[nb][lcol + 1][lrow] = av.y;
            As[nb][lcol + 2][lrow] = av.z; As[nb][lcol + 3][lrow] = av.w;
            Bs[nb][lcol + 0][lrow] = bv.x; Bs[nb][lcol + 1][lrow] = bv.y;
            Bs[nb][lcol + 2][lrow] = bv.z; Bs[nb][lcol + 3][lrow] = bv.w;
        }
        __syncthreads();
    }

    #pragma unroll
    for (int i = 0; i < 8; i++) {
        int m = m0 + ty * 8 + i;
        #pragma unroll
        for (int j = 0; j < 8; j++) {
            int n = n0 + tx * 8 + j;
            float vv = acc[i][j];
            if (wscale) vv *= wscale[n >> 7];
            if (bias)   vv += bias[n];
            if (act)    vv = 0.5f * vv * (1.0f + erff(vv * 0.7071067811865476f));
            C[(size_t)m * ldc + n] = vv;
        }
    }
}

// ---------------------------------------------------------------------------
// Double-buffered fp32 SGEMM NN (verbatim R9; causal K cap)
// ---------------------------------------------------------------------------
__global__ void __launch_bounds__(256, 2)
gemm_nn(const float* __restrict__ A, const float* __restrict__ Bm, float* __restrict__ C,
        int K, int lda, int ldb, int ldc,
        int zdiv, long long sA1, long long sA2, long long sB1, long long sB2,
        long long sC1, long long sC2, int causal)
{
    __shared__ float As[2][8][132];
    __shared__ float Bs[2][8][132];
    int z = blockIdx.z;
    int z1 = z / zdiv, z2 = z % zdiv;
    A  += z1 * sA1 + z2 * sA2;
    Bm += z1 * sB1 + z2 * sB2;
    C  += z1 * sC1 + z2 * sC2;
    int tid = threadIdx.x;
    int tx = tid & 15, ty = tid >> 4;
    int m0 = blockIdx.y * 128, n0 = blockIdx.x * 128;
    int arow = tid >> 1, acol = (tid & 1) * 4;
    int brow = tid >> 5, bcol = (tid & 31) * 4;
    const float* gA = A + (size_t)(m0 + arow) * lda + acol;
    const float* gB = Bm + (size_t)brow * ldb + n0 + bcol;

    int Keff = causal ? (m0 + 128 < K ? m0 + 128 : K) : K;

    float acc[8][8];
    #pragma unroll
    for (int i = 0; i < 8; i++)
        #pragma unroll
        for (int j = 0; j < 8; j++) acc[i][j] = 0.0f;

    float4 av = *reinterpret_cast<const float4*>(gA);
    float4 bv = *reinterpret_cast<const float4*>(gB);
    As[0][acol + 0][arow] = av.x; As[0][acol + 1][arow] = av.y;
    As[0][acol + 2][arow] = av.z; As[0][acol + 3][arow] = av.w;
    *reinterpret_cast<float4*>(&Bs[0][brow][bcol]) = bv;
    __syncthreads();

    int nkt = Keff >> 3;
    for (int kt = 0; kt < nkt; kt++) {
        int cur = kt & 1;
        bool pf = (kt + 1) < nkt;
        if (pf) {
            av = *reinterpret_cast<const float4*>(gA + (kt + 1) * 8);
            bv = *reinterpret_cast<const float4*>(gB + (size_t)(kt + 1) * 8 * ldb);
        }
        #pragma unroll
        for (int kk = 0; kk < 8; kk++) {
            float4 a0 = *reinterpret_cast<const float4*>(&As[cur][kk][ty * 8]);
            float4 a1 = *reinterpret_cast<const float4*>(&As[cur][kk][ty * 8 + 4]);
            float4 b0 = *reinterpret_cast<const float4*>(&Bs[cur][kk][tx * 8]);
            float4 b1 = *reinterpret_cast<const float4*>(&Bs[cur][kk][tx * 8 + 4]);
            float a[8] = {a0.x, a0.y, a0.z, a0.w, a1.x, a1.y, a1.z, a1.w};
            float b[8] = {b0.x, b0.y, b0.z, b0.w, b1.x, b1.y, b1.z, b1.w};
            #pragma unroll
            for (int i = 0; i < 8; i++)
                #pragma unroll
                for (int j = 0; j < 8; j++) acc[i][j] = fmaf(a[i], b[j], acc[i][j]);
        }
        if (pf) {
            int nb = cur ^ 1;
            As[nb][acol + 0][arow] = av.x; As[nb][acol + 1][arow] = av.y;
            As[nb][acol + 2][arow] = av.z; As[nb][acol + 3][arow] = av.w;
            *reinterpret_cast<float4*>(&Bs[nb][brow][bcol]) = bv;
        }
        __syncthreads();
    }

    #pragma unroll
    for (int i = 0; i < 8; i++) {
        int m = m0 + ty * 8 + i;
        #pragma unroll
        for (int j = 0; j < 8; j++) {
            int n = n0 + tx * 8 + j;
            C[(size_t)m * ldc + n] = acc[i][j];
        }
    }
}

// ---------------------------------------------------------------------------
// Causal-masked softmax — verbatim R1/R9
// ---------------------------------------------------------------------------
__global__ void softmax_kernel(float* __restrict__ S, const int* __restrict__ mask, float scale)
{
    int row = blockIdx.x;
    int q = row % Tt;
    int b = row / (Hh * Tt);
    float* sr = S + (size_t)row * Tt;
    const int* mr = mask + ((size_t)b * Tt + q) * Tt;
    int tid = threadIdx.x;
    __shared__ float red[256];
    float vals[4];
    float lmax = -INFINITY;
    #pragma unroll
    for (int it = 0; it < 4; it++) {
        int i = tid + it * 256;
        float v = mr[i] ? sr[i] * scale : -INFINITY;
        vals[it] = v;
        lmax = fmaxf(lmax, v);
    }
    red[tid] = lmax; __syncthreads();
    for (int o = 128; o > 0; o >>= 1) {
        if (tid < o) red[tid] = fmaxf(red[tid], red[tid + o]);
        __syncthreads();
    }
    float mx = red[0];
    __syncthreads();
    float lsum = 0.0f;
    #pragma unroll
    for (int it = 0; it < 4; it++) {
        float e = expf(vals[it] - mx);
        vals[it] = e;
        lsum += e;
    }
    red[tid] = lsum; __syncthreads();
    for (int o = 128; o > 0; o >>= 1) {
        if (tid < o) red[tid] += red[tid + o];
        __syncthreads();
    }
    float inv = 1.0f / red[0];
    #pragma unroll
    for (int it = 0; it < 4; it++) {
        int i = tid + it * 256;
        sr[i] = vals[it] * inv;
    }
}

// ---------------------------------------------------------------------------
// LayerNorm(x + y) — verbatim R1/R9
// ---------------------------------------------------------------------------
__global__ void addln_kernel(const float* __restrict__ x, const float* __restrict__ y,
                             float* __restrict__ out,
                             const float* __restrict__ g, const float* __restrict__ gs,
                             const float* __restrict__ b, const float* __restrict__ bs)
{
    int row = blockIdx.x;
    const float* xr = x + (size_t)row * Cdim;
    const float* yr = y + (size_t)row * Cdim;
    float* outr = out + (size_t)row * Cdim;
    __shared__ float buf[Cdim];
    __shared__ float red[256];
    int tid = threadIdx.x;
    float lsum = 0.0f;
    #pragma unroll
    for (int it = 0; it < Cdim / 256; it++) {
        int i = tid + it * 256;
        float v = xr[i] + yr[i];
        buf[i] = v;
        lsum += v;
    }
    red[tid] = lsum; __syncthreads();
    for (int o = 128; o > 0; o >>= 1) {
        if (tid < o) red[tid] += red[tid + o];
        __syncthreads();
    }
    float mean = red[0] * (1.0f / Cdim);
    __syncthreads();
    float lvar = 0.0f;
    #pragma unroll
    for (int it = 0; it < Cdim / 256; it++) {
        int i = tid + it * 256;
        float d = buf[i] - mean;
        lvar += d * d;
    }
    red[tid] = lvar; __syncthreads();
    for (int o = 128; o > 0; o >>= 1) {
        if (tid < o) red[tid] += red[tid + o];
        __syncthreads();
    }
    float rstd = rsqrtf(red[0] * (1.0f / Cdim) + 1e-5f);
    #pragma unroll
    for (int it = 0; it < Cdim / 256; it++) {
        int i = tid + it * 256;
        float d = (buf[i] - mean) * rstd;
        outr[i] = d * (g[i] * gs[i >> 7]) + b[i] * bs[i >> 7];
    }
}

// ---------------------------------------------------------------------------
// Launch pipeline
// ---------------------------------------------------------------------------
extern "C" void kernel_launch(void* const* d_in, const int* in_sizes, int n_in,
                              void* d_out, int out_size)
{
    const float* x     = (const float*)d_in[0];
    const int*   mask  = (const int*)  d_in[1];
    const float* wq    = (const float*)d_in[2];
    const float* qs    = (const float*)d_in[3];
    const float* wk    = (const float*)d_in[4];
    const float* ks    = (const float*)d_in[5];
    const float* wv    = (const float*)d_in[6];
    const float* vs    = (const float*)d_in[7];
    const float* wo    = (const float*)d_in[8];
    const float* os_   = (const float*)d_in[9];
    const float* fc1w  = (const float*)d_in[10];
    const float* fc1s  = (const float*)d_in[11];
    const float* fc1b  = (const float*)d_in[12];
    const float* fc2w  = (const float*)d_in[13];
    const float* fc2s  = (const float*)d_in[14];
    const float* fc2b  = (const float*)d_in[15];
    const float* l1g   = (const float*)d_in[16];
    const float* l1gs  = (const float*)d_in[17];
    const float* l1b   = (const float*)d_in[18];
    const float* l1bs  = (const float*)d_in[19];
    const float* l2g   = (const float*)d_in[20];
    const float* l2gs  = (const float*)d_in[21];
    const float* l2b   = (const float*)d_in[22];
    const float* l2bs  = (const float*)d_in[23];
    float* out = (float*)d_out;

    void* p;
    cudaGetSymbolAddress(&p, g_xdq);    float* xdq = (float*)p;
    cudaGetSymbolAddress(&p, g_hdq);    float* hdq = (float*)p;
    cudaGetSymbolAddress(&p, g_q);      float* qb  = (float*)p;
    cudaGetSymbolAddress(&p, g_k);      float* kb  = (float*)p;
    cudaGetSymbolAddress(&p, g_v);      float* vb  = (float*)p;
    cudaGetSymbolAddress(&p, g_scores); float* sc  = (float*)p;
    cudaGetSymbolAddress(&p, g_ctx);    float* ctx = (float*)p;
    cudaGetSymbolAddress(&p, g_tmp);    float* tmp = (float*)p;
    cudaGetSymbolAddress(&p, g_x1);     float* x1  = (float*)p;
    cudaGetSymbolAddress(&p, g_h);      float* hb  = (float*)p;
    cudaGetSymbolAddress(&p, g_ffn);    float* ffn = (float*)p;
    cudaGetSymbolAddress(&p, g_f2h);    __half* f2h = (__half*)p;

    cudaFuncSetAttribute(wgemm, cudaFuncAttributeMaxDynamicSharedMemorySize, W_SMEM);

    const float E5MAX = 57344.0f, E4MAX = 448.0f;
    const float INV_SQRT_HD = 0.08838834764831845f;

    // fc2 weight -> fp16 (exact)
    int nmc = MLPD * Cdim / 4;
    conv_f16<<<(nmc + 255) / 256, 256>>>(fc2w, f2h, nmc);

    // 1. qdq x (E5M2)
    qdq_kernel<<<(Mrows * Cdim / 128) / 8, 256>>>(x, xdq, E5MAX, 0);

    // 2. QKV projections (fp32)
    dim3 gl(Cdim / 128, Mrows / 128, 1);
    gemm_nt<<<gl, 256>>>(xdq, wq, qb, Cdim, Cdim, Cdim, Cdim,
                         1, 0, 0, 0, 0, 0, 0, qs, nullptr, 0, 0);
    gemm_nt<<<gl, 256>>>(xdq, wk, kb, Cdim, Cdim, Cdim, Cdim,
                         1, 0, 0, 0, 0, 0, 0, ks, nullptr, 0, 0);
    gemm_nt<<<gl, 256>>>(xdq, wv, vb, Cdim, Cdim, Cdim, Cdim,
                         1, 0, 0, 0, 0, 0, 0, vs, nullptr, 0, 0);

    // 3. scores = Q @ K^T (causal tiles only)
    dim3 gsc(Tt / 128, Tt / 128, Bb * Hh);
    gemm_nt<<<gsc, 256>>>(qb, kb, sc, HDim, Cdim, Cdim, Tt,
                          Hh, (long long)Tt * Cdim, 128, (long long)Tt * Cdim, 128,
                          (long long)Hh * Tt * Tt, (long long)Tt * Tt,
                          nullptr, nullptr, 0, 1);

    // 4. masked softmax
    softmax_kernel<<<Bb * Hh * Tt, 256>>>(sc, mask, INV_SQRT_HD);

    // 5. ctx = attn @ V (K capped causally)
    dim3 gcx(1, Tt / 128, Bb * Hh);
    gemm_nn<<<gcx, 256>>>(sc, vb, ctx, Tt, Tt, Cdim, Cdim,
                          Hh, (long long)Hh * Tt * Tt, (long long)Tt * Tt,
                          (long long)Tt * Cdim, 128, (long long)Tt * Cdim, 128, 1);

    // 6. out projection (fp32)
    qdq_kernel<<<(Mrows * Cdim / 128) / 8, 256>>>(ctx, xdq, E5MAX, 0);
    gemm_nt<<<gl, 256>>>(xdq, wo, tmp, Cdim, Cdim, Cdim, Cdim,
                         1, 0, 0, 0, 0, 0, 0, os_, nullptr, 0, 0);

    // 7. x1 = LN1(x + attn_out)
    addln_kernel<<<Mrows, 256>>>(x, tmp, x1, l1g, l1gs, l1b, l1bs);

    // 8. fc1 + bias + exact GELU (fp32 — output feeds qdq, flip-sensitive)
    qdq_kernel<<<(Mrows * Cdim / 128) / 8, 256>>>(x1, xdq, E4MAX, 1);
    dim3 gf1(MLPD / 128, Mrows / 128, 1);
    gemm_nt<<<gf1, 256>>>(xdq, fc1w, hb, Cdim, Cdim, Cdim, MLPD,
                          1, 0, 0, 0, 0, 0, 0, fc1s, fc1b, 1, 0);

    // 9. fc2 via split-fp16 tensor cores (no qdq downstream -> flip-safe probe)
    qdq_kernel<<<(Mrows * MLPD / 128) / 8, 256>>>(hb, hdq, E4MAX, 1);
    dim3 gf2(Cdim / 128, Mrows / 128, 1);
    wgemm<<<gf2, 512, W_SMEM>>>(hdq, f2h, ffn, MLPD, Cdim, fc2s, fc2b, 0);

    // 10. out = LN2(x1 + ffn)
    addln_kernel<<<Mrows, 256>>>(x1, ffn, out, l2g, l2gs, l2b, l2bs);
}

// round 12
// speedup vs baseline: 1.3366x; 1.3366x over previous
#include <cuda_runtime.h>
#include <cuda_fp8.h>
#include <cuda_fp16.h>
#include <cstdint>
#include <math.h>

#define Bb 2
#define Tt 1024
#define Cdim 2048
#define Hh 16
#define HDim 128
#define MLPD 8192
#define Mrows (Bb * Tt)

__device__ float g_xdq[Mrows * Cdim];
__device__ float g_hdq[Mrows * MLPD];
__device__ float g_q[Mrows * Cdim];
__device__ float g_k[Mrows * Cdim];
__device__ float g_v[Mrows * Cdim];
__device__ float g_scores[(size_t)Bb * Hh * Tt * Tt];
__device__ float g_ctx[Mrows * Cdim];
__device__ float g_tmp[Mrows * Cdim];
__device__ float g_x1[Mrows * Cdim];
__device__ float g_h[Mrows * MLPD];
__device__ float g_ffn[Mrows * Cdim];

// ---------------------------------------------------------------------------
// Packed f32x2 helpers (B300 dual-lane fp32 FMA; PTX sm_100+ baseline)
// Each lane is an independent IEEE fp32 fma -> lane-wise results are
// bit-identical to scalar fmaf sequences.
// ---------------------------------------------------------------------------
typedef unsigned long long u64t;
__device__ __forceinline__ u64t pk2(float lo, float hi) {
    u64t d;
    asm("mov.b64 %0, {%1,%2};" : "=l"(d) : "f"(lo), "f"(hi));
    return d;
}
__device__ __forceinline__ void upk2(float& lo, float& hi, u64t d) {
    asm("mov.b64 {%0,%1}, %2;" : "=f"(lo), "=f"(hi) : "l"(d));
}
__device__ __forceinline__ void fma2(u64t& c, u64t a, u64t b) {
    asm("fma.rn.f32x2 %0, %1, %2, %0;" : "+l"(c) : "l"(a), "l"(b));
}

// ---------------------------------------------------------------------------
// fp32 quantize-dequantize (bit-identical to passing R1/R9)
// ---------------------------------------------------------------------------
__global__ void qdq_kernel(const float* __restrict__ in, float* __restrict__ out,
                           float fmax, int e4m3)
{
    int blk  = blockIdx.x * 8 + (threadIdx.x >> 5);
    int lane = threadIdx.x & 31;
    size_t base = (size_t)blk * 128 + (size_t)lane * 4;
    float4 v = *reinterpret_cast<const float4*>(in + base);
    float am = fmaxf(fmaxf(fabsf(v.x), fabsf(v.y)), fmaxf(fabsf(v.z), fabsf(v.w)));
    #pragma unroll
    for (int o = 16; o > 0; o >>= 1)
        am = fmaxf(am, __shfl_xor_sync(0xffffffffu, am, o));
    float s = fmaxf(am / fmax, 1e-12f);
    float r4[4]; float xin[4] = {v.x, v.y, v.z, v.w};
    #pragma unroll
    for (int i = 0; i < 4; i++) {
        float r = xin[i] / s;
        __nv_fp8_storage_t f8 = __nv_cvt_float_to_fp8(r, __NV_SATFINITE, e4m3 ? __NV_E4M3 : __NV_E5M2);
        __half_raw hr = __nv_cvt_fp8_to_halfraw(f8, e4m3 ? __NV_E4M3 : __NV_E5M2);
        r4[i] = __half2float(*reinterpret_cast<__half*>(&hr)) * s;
    }
    float4 o4 = {r4[0], r4[1], r4[2], r4[3]};
    *reinterpret_cast<float4*>(out + base) = o4;
}

// ---------------------------------------------------------------------------
// Double-buffered fp32 SGEMM NT with f32x2 dual-lane FMA inner loop.
// Lane-wise accumulation order identical to R9 -> bit-identical results.
// causal: skip tiles with n0 > m0+127.
// ---------------------------------------------------------------------------
__global__ void __launch_bounds__(256, 2)
gemm_nt(const float* __restrict__ A, const float* __restrict__ W, float* __restrict__ C,
        int K, int lda, int ldb, int ldc,
        int zdiv, long long sA1, long long sA2, long long sB1, long long sB2,
        long long sC1, long long sC2,
        const float* __restrict__ wscale, const float* __restrict__ bias,
        int act, int causal)
{
    __shared__ float As[2][8][132];
    __shared__ float Bs[2][8][132];
    int z = blockIdx.z;
    int z1 = z / zdiv, z2 = z % zdiv;
    A += z1 * sA1 + z2 * sA2;
    W += z1 * sB1 + z2 * sB2;
    C += z1 * sC1 + z2 * sC2;

    int m0 = blockIdx.y * 128, n0 = blockIdx.x * 128;
    if (causal && n0 > m0 + 127) return;

    int tid = threadIdx.x;
    int tx = tid & 15, ty = tid >> 4;
    int lrow = tid >> 1, lcol = (tid & 1) * 4;
    const float* gA = A + (size_t)(m0 + lrow) * lda + lcol;
    const float* gB = W + (size_t)(n0 + lrow) * ldb + lcol;

    u64t acc2[8][4];
    #pragma unroll
    for (int i = 0; i < 8; i++)
        #pragma unroll
        for (int j = 0; j < 4; j++) acc2[i][j] = 0ull;

    float4 av = *reinterpret_cast<const float4*>(gA);
    float4 bv = *reinterpret_cast<const float4*>(gB);
    As[0][lcol + 0][lrow] = av.x; As[0][lcol + 1][lrow] = av.y;
    As[0][lcol + 2][lrow] = av.z; As[0][lcol + 3][lrow] = av.w;
    Bs[0][lcol + 0][lrow] = bv.x; Bs[0][lcol + 1][lrow] = bv.y;
    Bs[0][lcol + 2][lrow] = bv.z; Bs[0][lcol + 3][lrow] = bv.w;
    __syncthreads();

    int nkt = K >> 3;
    for (int kt = 0; kt < nkt; kt++) {
        int cur = kt & 1;
        bool pf = (kt + 1) < nkt;
        if (pf) {
            av = *reinterpret_cast<const float4*>(gA + (kt + 1) * 8);
            bv = *reinterpret_cast<const float4*>(gB + (kt + 1) * 8);
        }
        #pragma unroll
        for (int kk = 0; kk < 8; kk++) {
            float4 a0 = *reinterpret_cast<const float4*>(&As[cur][kk][ty * 8]);
            float4 a1 = *reinterpret_cast<const float4*>(&As[cur][kk][ty * 8 + 4]);
            float4 b0 = *reinterpret_cast<const float4*>(&Bs[cur][kk][tx * 8]);
            float4 b1 = *reinterpret_cast<const float4*>(&Bs[cur][kk][tx * 8 + 4]);
            float a[8] = {a0.x, a0.y, a0.z, a0.w, a1.x, a1.y, a1.z, a1.w};
            u64t ad[8], bd[4];
            #pragma unroll
            for (int i = 0; i < 8; i++) ad[i] = pk2(a[i], a[i]);
            bd[0] = pk2(b0.x, b0.y); bd[1] = pk2(b0.z, b0.w);
            bd[2] = pk2(b1.x, b1.y); bd[3] = pk2(b1.z, b1.w);
            #pragma unroll
            for (int i = 0; i < 8; i++)
                #pragma unroll
                for (int j = 0; j < 4; j++) fma2(acc2[i][j], ad[i], bd[j]);
        }
        if (pf) {
            int nb = cur ^ 1;
            As[nb][lcol + 0][lrow] = av.x; As[nb][lcol + 1][lrow] = av.y;
            As[nb][lcol + 2][lrow] = av.z; As[nb][lcol + 3][lrow] = av.w;
            Bs[nb][lcol + 0][lrow] = bv.x; Bs[nb][lcol + 1][lrow] = bv.y;
            Bs[nb][lcol + 2][lrow] = bv.z; Bs[nb][lcol + 3][lrow] = bv.w;
        }
        __syncthreads();
    }

    #pragma unroll
    for (int i = 0; i < 8; i++) {
        int m = m0 + ty * 8 + i;
        #pragma unroll
        for (int j = 0; j < 4; j++) {
            float vlo, vhi;
            upk2(vlo, vhi, acc2[i][j]);
            int n = n0 + tx * 8 + j * 2;
            float ws0 = wscale ? wscale[n >> 7] : 1.0f;
            float ws1 = wscale ? wscale[(n + 1) >> 7] : 1.0f;
            vlo *= ws0; vhi *= ws1;
            if (bias) { vlo += bias[n]; vhi += bias[n + 1]; }
            if (act) {
                vlo = 0.5f * vlo * (1.0f + erff(vlo * 0.7071067811865476f));
                vhi = 0.5f * vhi * (1.0f + erff(vhi * 0.7071067811865476f));
            }
            C[(size_t)m * ldc + n]     = vlo;
            C[(size_t)m * ldc + n + 1] = vhi;
        }
    }
}

// ---------------------------------------------------------------------------
// Double-buffered fp32 SGEMM NN (attn @ V) with f32x2 inner loop.
// Exact causal K cap at m0+128.
// ---------------------------------------------------------------------------
__global__ void __launch_bounds__(256, 2)
gemm_nn(const float* __restrict__ A, const float* __restrict__ Bm, float* __restrict__ C,
        int K, int lda, int ldb, int ldc,
        int zdiv, long long sA1, long long sA2, long long sB1, long long sB2,
        long long sC1, long long sC2, int causal)
{
    __shared__ float As[2][8][132];
    __shared__ float Bs[2][8][132];
    int z = blockIdx.z;
    int z1 = z / zdiv, z2 = z % zdiv;
    A  += z1 * sA1 + z2 * sA2;
    Bm += z1 * sB1 + z2 * sB2;
    C  += z1 * sC1 + z2 * sC2;
    int tid = threadIdx.x;
    int tx = tid & 15, ty = tid >> 4;
    int m0 = blockIdx.y * 128, n0 = blockIdx.x * 128;
    int arow = tid >> 1, acol = (tid & 1) * 4;
    int brow = tid >> 5, bcol = (tid & 31) * 4;
    const float* gA = A + (size_t)(m0 + arow) * lda + acol;
    const float* gB = Bm + (size_t)brow * ldb + n0 + bcol;

    int Keff = causal ? (m0 + 128 < K ? m0 + 128 : K) : K;

    u64t acc2[8][4];
    #pragma unroll
    for (int i = 0; i < 8; i++)
        #pragma unroll
        for (int j = 0; j < 4; j++) acc2[i][j] = 0ull;

    float4 av = *reinterpret_cast<const float4*>(gA);
    float4 bv = *reinterpret_cast<const float4*>(gB);
    As[0][acol + 0][arow] = av.x; As[0][acol + 1][arow] = av.y;
    As[0][acol + 2][arow] = av.z; As[0][acol + 3][arow] = av.w;
    *reinterpret_cast<float4*>(&Bs[0][brow][bcol]) = bv;
    __syncthreads();

    int nkt = Keff >> 3;
    for (int kt = 0; kt < nkt; kt++) {
        int cur = kt & 1;
        bool pf = (kt + 1) < nkt;
        if (pf) {
            av = *reinterpret_cast<const float4*>(gA + (kt + 1) * 8);
            bv = *reinterpret_cast<const float4*>(gB + (size_t)(kt + 1) * 8 * ldb);
        }
        #pragma unroll
        for (int kk = 0; kk < 8; kk++) {
            float4 a0 = *reinterpret_cast<const float4*>(&As[cur][kk][ty * 8]);
            float4 a1 = *reinterpret_cast<const float4*>(&As[cur][kk][ty * 8 + 4]);
            float4 b0 = *reinterpret_cast<const float4*>(&Bs[cur][kk][tx * 8]);
            float4 b1 = *reinterpret_cast<const float4*>(&Bs[cur][kk][tx * 8 + 4]);
            float a[8] = {a0.x, a0.y, a0.z, a0.w, a1.x, a1.y, a1.z, a1.w};
            u64t ad[8], bd[4];
            #pragma unroll
            for (int i = 0; i < 8; i++) ad[i] = pk2(a[i], a[i]);
            bd[0] = pk2(b0.x, b0.y); bd[1] = pk2(b0.z, b0.w);
            bd[2] = pk2(b1.x, b1.y); bd[3] = pk2(b1.z, b1.w);
            #pragma unroll
            for (int i = 0; i < 8; i++)
                #pragma unroll
                for (int j = 0; j < 4; j++) fma2(acc2[i][j], ad[i], bd[j]);
        }
        if (pf) {
            int nb = cur ^ 1;
            As[nb][acol + 0][arow] = av.x; As[nb][acol + 1][arow] = av.y;
            As[nb][acol + 2][arow] = av.z; As[nb][acol + 3][arow] = av.w;
            *reinterpret_cast<float4*>(&Bs[nb][brow][bcol]) = bv;
        }
        __syncthreads();
    }

    #pragma unroll
    for (int i = 0; i < 8; i++) {
        int m = m0 + ty * 8 + i;
        #pragma unroll
        for (int j = 0; j < 4; j++) {
            float vlo, vhi;
            upk2(vlo, vhi, acc2[i][j]);
            int n = n0 + tx * 8 + j * 2;
            C[(size_t)m * ldc + n]     = vlo;
            C[(size_t)m * ldc + n + 1] = vhi;
        }
    }
}

// ---------------------------------------------------------------------------
// Causal-masked softmax — verbatim R1/R9
// ---------------------------------------------------------------------------
__global__ void softmax_kernel(float* __restrict__ S, const int* __restrict__ mask, float scale)
{
    int row = blockIdx.x;
    int q = row % Tt;
    int b = row / (Hh * Tt);
    float* sr = S + (size_t)row * Tt;
    const int* mr = mask + ((size_t)b * Tt + q) * Tt;
    int tid = threadIdx.x;
    __shared__ float red[256];
    float vals[4];
    float lmax = -INFINITY;
    #pragma unroll
    for (int it = 0; it < 4; it++) {
        int i = tid + it * 256;
        float v = mr[i] ? sr[i] * scale : -INFINITY;
        vals[it] = v;
        lmax = fmaxf(lmax, v);
    }
    red[tid] = lmax; __syncthreads();
    for (int o = 128; o > 0; o >>= 1) {
        if (tid < o) red[tid] = fmaxf(red[tid], red[tid + o]);
        __syncthreads();
    }
    float mx = red[0];
    __syncthreads();
    float lsum = 0.0f;
    #pragma unroll
    for (int it = 0; it < 4; it++) {
        float e = expf(vals[it] - mx);
        vals[it] = e;
        lsum += e;
    }
    red[tid] = lsum; __syncthreads();
    for (int o = 128; o > 0; o >>= 1) {
        if (tid < o) red[tid] += red[tid + o];
        __syncthreads();
    }
    float inv = 1.0f / red[0];
    #pragma unroll
    for (int it = 0; it < 4; it++) {
        int i = tid + it * 256;
        sr[i] = vals[it] * inv;
    }
}

// ---------------------------------------------------------------------------
// LayerNorm(x + y) — verbatim R1/R9
// ---------------------------------------------------------------------------
__global__ void addln_kernel(const float* __restrict__ x, const float* __restrict__ y,
                             float* __restrict__ out,
                             const float* __restrict__ g, const float* __restrict__ gs,
                             const float* __restrict__ b, const float* __restrict__ bs)
{
    int row = blockIdx.x;
    const float* xr = x + (size_t)row * Cdim;
    const float* yr = y + (size_t)row * Cdim;
    float* outr = out + (size_t)row * Cdim;
    __shared__ float buf[Cdim];
    __shared__ float red[256];
    int tid = threadIdx.x;
    float lsum = 0.0f;
    #pragma unroll
    for (int it = 0; it < Cdim / 256; it++) {
        int i = tid + it * 256;
        float v = xr[i] + yr[i];
        buf[i] = v;
        lsum += v;
    }
    red[tid] = lsum; __syncthreads();
    for (int o = 128; o > 0; o >>= 1) {
        if (tid < o) red[tid] += red[tid + o];
        __syncthreads();
    }
    float mean = red[0] * (1.0f / Cdim);
    __syncthreads();
    float lvar = 0.0f;
    #pragma unroll
    for (int it = 0; it < Cdim / 256; it++) {
        int i = tid + it * 256;
        float d = buf[i] - mean;
        lvar += d * d;
    }
    red[tid] = lvar; __syncthreads();
    for (int o = 128; o > 0; o >>= 1) {
        if (tid < o) red[tid] += red[tid + o];
        __syncthreads();
    }
    float rstd = rsqrtf(red[0] * (1.0f / Cdim) + 1e-5f);
    #pragma unroll
    for (int it = 0; it < Cdim / 256; it++) {
        int i = tid + it * 256;
        float d = (buf[i] - mean) * rstd;
        outr[i] = d * (g[i] * gs[i >> 7]) + b[i] * bs[i >> 7];
    }
}

// ---------------------------------------------------------------------------
// Launch pipeline
// ---------------------------------------------------------------------------
extern "C" void kernel_launch(void* const* d_in, const int* in_sizes, int n_in,
                              void* d_out, int out_size)
{
    const float* x     = (const float*)d_in[0];
    const int*   mask  = (const int*)  d_in[1];
    const float* wq    = (const float*)d_in[2];
    const float* qs    = (const float*)d_in[3];
    const float* wk    = (const float*)d_in[4];
    const float* ks    = (const float*)d_in[5];
    const float* wv    = (const float*)d_in[6];
    const float* vs    = (const float*)d_in[7];
    const float* wo    = (const float*)d_in[8];
    const float* os_   = (const float*)d_in[9];
    const float* fc1w  = (const float*)d_in[10];
    const float* fc1s  = (const float*)d_in[11];
    const float* fc1b  = (const float*)d_in[12];
    const float* fc2w  = (const float*)d_in[13];
    const float* fc2s  = (const float*)d_in[14];
    const float* fc2b  = (const float*)d_in[15];
    const float* l1g   = (const float*)d_in[16];
    const float* l1gs  = (const float*)d_in[17];
    const float* l1b   = (const float*)d_in[18];
    const float* l1bs  = (const float*)d_in[19];
    const float* l2g   = (const float*)d_in[20];
    const float* l2gs  = (const float*)d_in[21];
    const float* l2b   = (const float*)d_in[22];
    const float* l2bs  = (const float*)d_in[23];
    float* out = (float*)d_out;

    void* p;
    cudaGetSymbolAddress(&p, g_xdq);    float* xdq = (float*)p;
    cudaGetSymbolAddress(&p, g_hdq);    float* hdq = (float*)p;
    cudaGetSymbolAddress(&p, g_q);      float* qb  = (float*)p;
    cudaGetSymbolAddress(&p, g_k);      float* kb  = (float*)p;
    cudaGetSymbolAddress(&p, g_v);      float* vb  = (float*)p;
    cudaGetSymbolAddress(&p, g_scores); float* sc  = (float*)p;
    cudaGetSymbolAddress(&p, g_ctx);    float* ctx = (float*)p;
    cudaGetSymbolAddress(&p, g_tmp);    float* tmp = (float*)p;
    cudaGetSymbolAddress(&p, g_x1);     float* x1  = (float*)p;
    cudaGetSymbolAddress(&p, g_h);      float* hb  = (float*)p;
    cudaGetSymbolAddress(&p, g_ffn);    float* ffn = (float*)p;

    const float E5MAX = 57344.0f, E4MAX = 448.0f;
    const float INV_SQRT_HD = 0.08838834764831845f;

    // 1. qdq x (E5M2)
    qdq_kernel<<<(Mrows * Cdim / 128) / 8, 256>>>(x, xdq, E5MAX, 0);

    // 2. QKV projections
    dim3 gl(Cdim / 128, Mrows / 128, 1);
    gemm_nt<<<gl, 256>>>(xdq, wq, qb, Cdim, Cdim, Cdim, Cdim,
                         1, 0, 0, 0, 0, 0, 0, qs, nullptr, 0, 0);
    gemm_nt<<<gl, 256>>>(xdq, wk, kb, Cdim, Cdim, Cdim, Cdim,
                         1, 0, 0, 0, 0, 0, 0, ks, nullptr, 0, 0);
    gemm_nt<<<gl, 256>>>(xdq, wv, vb, Cdim, Cdim, Cdim, Cdim,
                         1, 0, 0, 0, 0, 0, 0, vs, nullptr, 0, 0);

    // 3. scores = Q @ K^T (causal tiles only)
    dim3 gsc(Tt / 128, Tt / 128, Bb * Hh);
    gemm_nt<<<gsc, 256>>>(qb, kb, sc, HDim, Cdim, Cdim, Tt,
                          Hh, (long long)Tt * Cdim, 128, (long long)Tt * Cdim, 128,
                          (long long)Hh * Tt * Tt, (long long)Tt * Tt,
                          nullptr, nullptr, 0, 1);

    // 4. masked softmax
    softmax_kernel<<<Bb * Hh * Tt, 256>>>(sc, mask, INV_SQRT_HD);

    // 5. ctx = attn @ V (K capped causally)
    dim3 gcx(1, Tt / 128, Bb * Hh);
    gemm_nn<<<gcx, 256>>>(sc, vb, ctx, Tt, Tt, Cdim, Cdim,
                          Hh, (long long)Hh * Tt * Tt, (long long)Tt * Tt,
                          (long long)Tt * Cdim, 128, (long long)Tt * Cdim, 128, 1);

    // 6. out projection
    qdq_kernel<<<(Mrows * Cdim / 128) / 8, 256>>>(ctx, xdq, E5MAX, 0);
    gemm_nt<<<gl, 256>>>(xdq, wo, tmp, Cdim, Cdim, Cdim, Cdim,
                         1, 0, 0, 0, 0, 0, 0, os_, nullptr, 0, 0);

    // 7. x1 = LN1(x + attn_out)
    addln_kernel<<<Mrows, 256>>>(x, tmp, x1, l1g, l1gs, l1b, l1bs);

    // 8. fc1 + bias + exact GELU
    qdq_kernel<<<(Mrows * Cdim / 128) / 8, 256>>>(x1, xdq, E4MAX, 1);
    dim3 gf1(MLPD / 128, Mrows / 128, 1);
    gemm_nt<<<gf1, 256>>>(xdq, fc1w, hb, Cdim, Cdim, Cdim, MLPD,
                          1, 0, 0, 0, 0, 0, 0, fc1s, fc1b, 1, 0);

    // 9. fc2 + bias (fp32 — wgemm reverted: correct but 2x slower than fp32)
    qdq_kernel<<<(Mrows * MLPD / 128) / 8, 256>>>(hb, hdq, E4MAX, 1);
    dim3 gf2(Cdim / 128, Mrows / 128, 1);
    gemm_nt<<<gf2, 256>>>(hdq, fc2w, ffn, MLPD, MLPD, MLPD, Cdim,
                          1, 0, 0, 0, 0, 0, 0, fc2s, fc2b, 0, 0);

    // 10. out = LN2(x1 + ffn)
    addln_kernel<<<Mrows, 256>>>(x1, ffn, out, l2g, l2gs, l2b, l2bs);
}